// round 6
// baseline (speedup 1.0000x reference)
#include <cuda_runtime.h>
#include <math.h>

#define NTOK 4096
#define HDIM 1024
#define FDIM 4096
#define NE   8

// ---------------- device scratch (no allocations allowed) ----------------
__device__ int   g_count[NE];
__device__ int   g_off[NE];
__device__ int   g_tok[NE * NTOK];
__device__ float g_wt[NE * NTOK];
__device__ float g_zsq[NTOK];
__device__ float g_wa[NTOK];   // top-1 softmax prob
__device__ float g_wb[NTOK];   // top-2 softmax prob
__device__ float g_ma[NTOK];   // mask for "class 0" (one_hot(num_classes=2) quirk)
__device__ float g_mb[NTOK];   // mask for "class 1"
__device__ __align__(16) float g_h1[(size_t)2 * NTOK * FDIM];  // 128 MiB hidden scratch

typedef unsigned long long u64;

__device__ __forceinline__ u64 pk2(float lo, float hi) {
    u64 r; asm("mov.b64 %0, {%1,%2};" : "=l"(r) : "f"(lo), "f"(hi)); return r;
}
__device__ __forceinline__ void fma2(u64& c, u64 a, u64 b) {
    asm("fma.rn.f32x2 %0, %1, %2, %0;" : "+l"(c) : "l"(a), "l"(b));
}
__device__ __forceinline__ float2 unpk(u64 v) {
    float2 f; asm("mov.b64 {%0,%1}, %2;" : "=f"(f.x), "=f"(f.y) : "l"(v)); return f;
}
__device__ __forceinline__ float silu_f(float v) {
    return v / (1.0f + expf(-v));
}

// ---------------- small kernels ----------------
__global__ void zero_kernel(float* out, int n) {
    for (int i = blockIdx.x * blockDim.x + threadIdx.x; i < n; i += gridDim.x * blockDim.x)
        out[i] = 0.0f;
}

__global__ void reset_kernel() {
    if (threadIdx.x < NE) g_count[threadIdx.x] = 0;
}

// One warp per token: router logits, softmax, top-2, stats, scatter.
__global__ void router_kernel(const float* __restrict__ x, const float* __restrict__ gw) {
    int warp = threadIdx.x >> 5;
    int lane = threadIdx.x & 31;
    int t = blockIdx.x * (blockDim.x >> 5) + warp;
    if (t >= NTOK) return;

    float p[NE];
#pragma unroll
    for (int e = 0; e < NE; e++) p[e] = 0.0f;

    const float* xr = x + (size_t)t * HDIM;
    for (int h = lane; h < HDIM; h += 32) {
        float xv = xr[h];
#pragma unroll
        for (int e = 0; e < NE; e++) p[e] += xv * gw[e * HDIM + h];
    }
#pragma unroll
    for (int e = 0; e < NE; e++) {
#pragma unroll
        for (int s = 16; s > 0; s >>= 1) p[e] += __shfl_xor_sync(0xffffffffu, p[e], s);
    }

    if (lane == 0) {
        float m = p[0];
#pragma unroll
        for (int e = 1; e < NE; e++) m = fmaxf(m, p[e]);
        float Z = 0.0f;
        float pr[NE];
#pragma unroll
        for (int e = 0; e < NE; e++) { pr[e] = expf(p[e] - m); Z += pr[e]; }
        float invZ = 1.0f / Z;
#pragma unroll
        for (int e = 0; e < NE; e++) pr[e] *= invZ;

        // top-2 (strict >: lowest index wins ties, matching jax top_k)
        int e1 = 0; float v1 = pr[0];
#pragma unroll
        for (int e = 1; e < NE; e++) if (pr[e] > v1) { v1 = pr[e]; e1 = e; }
        int e2 = -1; float v2 = -1.0f;
#pragma unroll
        for (int e = 0; e < NE; e++) if (e != e1 && pr[e] > v2) { v2 = pr[e]; e2 = e; }

        float s  = v1 + v2;
        float r1 = v1 / s, r2 = v2 / s;

        float lse = m + logf(Z);
        g_zsq[t] = lse * lse;
        g_wa[t]  = v1;
        g_wb[t]  = v2;
        g_ma[t]  = (e1 == 0 || e2 == 0) ? 1.0f : 0.0f;
        g_mb[t]  = (e1 == 1 || e2 == 1) ? 1.0f : 0.0f;

        int s1 = atomicAdd(&g_count[e1], 1);
        g_tok[e1 * NTOK + s1] = t; g_wt[e1 * NTOK + s1] = r1;
        int s2 = atomicAdd(&g_count[e2], 1);
        g_tok[e2 * NTOK + s2] = t; g_wt[e2 * NTOK + s2] = r2;
    }
}

// Single block: losses + prefix offsets.
__global__ void finalize_kernel(float* out, int out_size) {
    int tid = threadIdx.x;
    float s[5] = {0, 0, 0, 0, 0};
    for (int i = tid; i < NTOK; i += 256) {
        s[0] += g_zsq[i]; s[1] += g_wa[i]; s[2] += g_wb[i];
        s[3] += g_ma[i];  s[4] += g_mb[i];
    }
    __shared__ float red[256];
    __shared__ float tot[5];
#pragma unroll
    for (int q = 0; q < 5; q++) {
        red[tid] = s[q];
        __syncthreads();
        for (int st = 128; st > 0; st >>= 1) {
            if (tid < st) red[tid] += red[tid + st];
            __syncthreads();
        }
        if (tid == 0) tot[q] = red[0];
        __syncthreads();
    }
    if (tid == 0) {
        const float invT = 1.0f / (float)NTOK;
        float zl  = tot[0] * invT;
        float aux = 2.0f * ((tot[3] * invT) * (tot[1] * invT) +
                            (tot[4] * invT) * (tot[2] * invT));
        long long base = (long long)NTOK * HDIM;
        if ((long long)out_size > base)     out[base]     = zl;
        if ((long long)out_size > base + 1) out[base + 1] = aux;
        int o = 0;
        for (int e = 0; e < NE; e++) { g_off[e] = o; o += g_count[e]; }
    }
}

// ---------------- grouped GEMMs ----------------
// Tile: BM=128, BN=64, BK=16, 256 threads, 8x4 micro-tile, f32x2 FMA.

__global__ void __launch_bounds__(256)
gemm1_kernel(const float* __restrict__ x, const float* __restrict__ w1,
             const float* __restrict__ b1) {
    int e = blockIdx.z;
    int cnt = g_count[e];
    int m0 = blockIdx.y * 128;
    if (m0 >= cnt) return;
    int n0 = blockIdx.x * 64;

    __shared__ __align__(16) float As[16][132];
    __shared__ __align__(16) float Bs[16][64];
    __shared__ int toks[128];

    int tid = threadIdx.x;
    for (int i = tid; i < 128; i += 256) {
        int r = m0 + i; if (r > cnt - 1) r = cnt - 1;
        toks[i] = g_tok[e * NTOK + r];
    }
    __syncthreads();

    const float* Bp = w1 + (size_t)e * HDIM * FDIM + n0;
    int ar = tid >> 2, ac = (tid & 3) << 2;
    int bk = tid >> 4, bc = (tid & 15) << 2;

    const float* Arow0 = x + (size_t)toks[ar] * HDIM + ac;
    const float* Arow1 = x + (size_t)toks[ar + 64] * HDIM + ac;

    float4 a0 = *(const float4*)(Arow0);
    float4 a1 = *(const float4*)(Arow1);
    float4 bv = *(const float4*)(Bp + (size_t)bk * FDIM + bc);

    u64 c2[4][4];
#pragma unroll
    for (int j = 0; j < 4; j++)
#pragma unroll
        for (int n = 0; n < 4; n++) c2[j][n] = 0ull;

    int tx = tid & 15, ty = tid >> 4;
    const int NKT = HDIM / 16;

    for (int kt = 0; kt < NKT; ++kt) {
        As[ac + 0][ar] = a0.x; As[ac + 1][ar] = a0.y;
        As[ac + 2][ar] = a0.z; As[ac + 3][ar] = a0.w;
        As[ac + 0][ar + 64] = a1.x; As[ac + 1][ar + 64] = a1.y;
        As[ac + 2][ar + 64] = a1.z; As[ac + 3][ar + 64] = a1.w;
        *(float4*)&Bs[bk][bc] = bv;
        __syncthreads();

        if (kt + 1 < NKT) {
            int k0 = (kt + 1) * 16;
            a0 = *(const float4*)(Arow0 + k0);
            a1 = *(const float4*)(Arow1 + k0);
            bv = *(const float4*)(Bp + (size_t)(k0 + bk) * FDIM + bc);
        }

#pragma unroll
        for (int kk = 0; kk < 16; kk++) {
            const u64* ap = (const u64*)&As[kk][ty * 8];
            u64 a2_0 = ap[0], a2_1 = ap[1], a2_2 = ap[2], a2_3 = ap[3];
            float4 b4 = *(const float4*)&Bs[kk][tx * 4];
            u64 bb0 = pk2(b4.x, b4.x), bb1 = pk2(b4.y, b4.y);
            u64 bb2 = pk2(b4.z, b4.z), bb3 = pk2(b4.w, b4.w);
            fma2(c2[0][0], a2_0, bb0); fma2(c2[0][1], a2_0, bb1);
            fma2(c2[0][2], a2_0, bb2); fma2(c2[0][3], a2_0, bb3);
            fma2(c2[1][0], a2_1, bb0); fma2(c2[1][1], a2_1, bb1);
            fma2(c2[1][2], a2_1, bb2); fma2(c2[1][3], a2_1, bb3);
            fma2(c2[2][0], a2_2, bb0); fma2(c2[2][1], a2_2, bb1);
            fma2(c2[2][2], a2_2, bb2); fma2(c2[2][3], a2_2, bb3);
            fma2(c2[3][0], a2_3, bb0); fma2(c2[3][1], a2_3, bb1);
            fma2(c2[3][2], a2_3, bb2); fma2(c2[3][3], a2_3, bb3);
        }
        __syncthreads();
    }

    int off = g_off[e];
    const float* bbp = b1 + e * FDIM + n0 + tx * 4;
    float bias0 = bbp[0], bias1 = bbp[1], bias2 = bbp[2], bias3 = bbp[3];

#pragma unroll
    for (int j = 0; j < 4; j++) {
        float2 cc0 = unpk(c2[j][0]), cc1 = unpk(c2[j][1]);
        float2 cc2 = unpk(c2[j][2]), cc3 = unpk(c2[j][3]);
        int mA = m0 + ty * 8 + 2 * j;
        int mB = mA + 1;
        if (mA < cnt) {
            float4 v;
            v.x = silu_f(cc0.x + bias0); v.y = silu_f(cc1.x + bias1);
            v.z = silu_f(cc2.x + bias2); v.w = silu_f(cc3.x + bias3);
            *(float4*)&g_h1[(size_t)(off + mA) * FDIM + n0 + tx * 4] = v;
        }
        if (mB < cnt) {
            float4 v;
            v.x = silu_f(cc0.y + bias0); v.y = silu_f(cc1.y + bias1);
            v.z = silu_f(cc2.y + bias2); v.w = silu_f(cc3.y + bias3);
            *(float4*)&g_h1[(size_t)(off + mB) * FDIM + n0 + tx * 4] = v;
        }
    }
}

__global__ void __launch_bounds__(256)
gemm2_kernel(const float* __restrict__ w2, const float* __restrict__ b2,
             float* __restrict__ out) {
    int e = blockIdx.z;
    int cnt = g_count[e];
    int m0 = blockIdx.y * 128;
    if (m0 >= cnt) return;
    int n0 = blockIdx.x * 64;
    int off = g_off[e];

    __shared__ __align__(16) float As[16][132];
    __shared__ __align__(16) float Bs[16][64];

    int tid = threadIdx.x;
    int ar = tid >> 2, ac = (tid & 3) << 2;
    int bk = tid >> 4, bc = (tid & 15) << 2;

    int r0 = min(m0 + ar, cnt - 1);
    int r1 = min(m0 + ar + 64, cnt - 1);
    const float* Arow0 = g_h1 + (size_t)(off + r0) * FDIM + ac;
    const float* Arow1 = g_h1 + (size_t)(off + r1) * FDIM + ac;
    const float* Bp = w2 + (size_t)e * FDIM * HDIM + n0;

    float4 a0 = *(const float4*)(Arow0);
    float4 a1 = *(const float4*)(Arow1);
    float4 bv = *(const float4*)(Bp + (size_t)bk * HDIM + bc);

    u64 c2[4][4];
#pragma unroll
    for (int j = 0; j < 4; j++)
#pragma unroll
        for (int n = 0; n < 4; n++) c2[j][n] = 0ull;

    int tx = tid & 15, ty = tid >> 4;
    const int NKT = FDIM / 16;

    for (int kt = 0; kt < NKT; ++kt) {
        As[ac + 0][ar] = a0.x; As[ac + 1][ar] = a0.y;
        As[ac + 2][ar] = a0.z; As[ac + 3][ar] = a0.w;
        As[ac + 0][ar + 64] = a1.x; As[ac + 1][ar + 64] = a1.y;
        As[ac + 2][ar + 64] = a1.z; As[ac + 3][ar + 64] = a1.w;
        *(float4*)&Bs[bk][bc] = bv;
        __syncthreads();

        if (kt + 1 < NKT) {
            int k0 = (kt + 1) * 16;
            a0 = *(const float4*)(Arow0 + k0);
            a1 = *(const float4*)(Arow1 + k0);
            bv = *(const float4*)(Bp + (size_t)(k0 + bk) * HDIM + bc);
        }

#pragma unroll
        for (int kk = 0; kk < 16; kk++) {
            const u64* ap = (const u64*)&As[kk][ty * 8];
            u64 a2_0 = ap[0], a2_1 = ap[1], a2_2 = ap[2], a2_3 = ap[3];
            float4 b4 = *(const float4*)&Bs[kk][tx * 4];
            u64 bb0 = pk2(b4.x, b4.x), bb1 = pk2(b4.y, b4.y);
            u64 bb2 = pk2(b4.z, b4.z), bb3 = pk2(b4.w, b4.w);
            fma2(c2[0][0], a2_0, bb0); fma2(c2[0][1], a2_0, bb1);
            fma2(c2[0][2], a2_0, bb2); fma2(c2[0][3], a2_0, bb3);
            fma2(c2[1][0], a2_1, bb0); fma2(c2[1][1], a2_1, bb1);
            fma2(c2[1][2], a2_1, bb2); fma2(c2[1][3], a2_1, bb3);
            fma2(c2[2][0], a2_2, bb0); fma2(c2[2][1], a2_2, bb1);
            fma2(c2[2][2], a2_2, bb2); fma2(c2[2][3], a2_2, bb3);
            fma2(c2[3][0], a2_3, bb0); fma2(c2[3][1], a2_3, bb1);
            fma2(c2[3][2], a2_3, bb2); fma2(c2[3][3], a2_3, bb3);
        }
        __syncthreads();
    }

    const float* bbp = b2 + e * HDIM + n0 + tx * 4;
    float bias0 = bbp[0], bias1 = bbp[1], bias2 = bbp[2], bias3 = bbp[3];

#pragma unroll
    for (int j = 0; j < 4; j++) {
        float2 cc0 = unpk(c2[j][0]), cc1 = unpk(c2[j][1]);
        float2 cc2 = unpk(c2[j][2]), cc3 = unpk(c2[j][3]);
        int mA = m0 + ty * 8 + 2 * j;
        int mB = mA + 1;
        int colb = n0 + tx * 4;
        if (mA < cnt) {
            int tok = g_tok[e * NTOK + mA];
            float wt = g_wt[e * NTOK + mA];
            float* op = out + (size_t)tok * HDIM + colb;
            atomicAdd(op + 0, wt * (cc0.x + bias0));
            atomicAdd(op + 1, wt * (cc1.x + bias1));
            atomicAdd(op + 2, wt * (cc2.x + bias2));
            atomicAdd(op + 3, wt * (cc3.x + bias3));
        }
        if (mB < cnt) {
            int tok = g_tok[e * NTOK + mB];
            float wt = g_wt[e * NTOK + mB];
            float* op = out + (size_t)tok * HDIM + colb;
            atomicAdd(op + 0, wt * (cc0.y + bias0));
            atomicAdd(op + 1, wt * (cc1.y + bias1));
            atomicAdd(op + 2, wt * (cc2.y + bias2));
            atomicAdd(op + 3, wt * (cc3.y + bias3));
        }
    }
}

// ---------------- launch ----------------
extern "C" void kernel_launch(void* const* d_in, const int* in_sizes, int n_in,
                              void* d_out, int out_size) {
    const float* x  = (const float*)d_in[0];
    const float* gw = (const float*)d_in[1];
    const float* w1 = (const float*)d_in[2];
    const float* b1 = (const float*)d_in[3];
    const float* w2 = (const float*)d_in[4];
    const float* b2 = (const float*)d_in[5];
    float* out = (float*)d_out;

    zero_kernel<<<2048, 256>>>(out, out_size);
    reset_kernel<<<1, 32>>>();
    router_kernel<<<NTOK / 8, 256>>>(x, gw);
    finalize_kernel<<<1, 256>>>(out, out_size);
    gemm1_kernel<<<dim3(FDIM / 64, NTOK / 128, NE), 256>>>(x, w1, b1);
    gemm2_kernel<<<dim3(HDIM / 64, NTOK / 128, NE), 256>>>(w2, b2, out);
}